// round 9
// baseline (speedup 1.0000x reference)
#include <cuda_runtime.h>
#include <cuda_bf16.h>

// SoftTimeAttention: out[b,i,:] = sum_j w_ij * h[b,j,:],
//   w_ij = softmax_j( -(T*(t_i - t_j))^2 ), T=4096, tau=1.
// Only ~13/4096 keys per query have fp32-visible weight (cutoff d^2<=40
// drops <2e-14 relative mass; self key weight is exactly 1, sumw >= 1).
//
// Pipeline: zero-hist -> histogram (B*4 CTAs) -> per-batch scan (B CTAs)
//           -> scatter (B*4 CTAs) -> attention gather.
// Attention: one warp per (4 consecutive sorted queries) x (half of H).
//   R5 ncu: occ=28%, all pipes <22% -> latency-bound. H-split doubles warps
//   and halves regs, traffic-neutral.

#define TT 4096            // sequence length (== softmax scale T)
#define HH 256             // head dim
#define NB 4096            // buckets
#define RADIUS 7           // ceil(sqrt(40)/TT * NB) = 7
#define CUTF 40.0f
#define MAXB 8
#define QPW 4              // sorted queries per warp

__device__ float g_ct  [MAXB * TT];         // t values reordered by bucket
__device__ int   g_cidx[MAXB * TT];         // original indices reordered
__device__ int   g_hist[MAXB * NB];         // per-batch histogram
__device__ int   g_cur [MAXB * NB];         // scatter cursors
__device__ int   g_bstart[MAXB * (NB + 1)]; // bucket start offsets (+ total)

__device__ __forceinline__ int bucket_of(float v) {
    int bi = (int)(v * (float)NB);
    bi = bi < 0 ? 0 : bi;
    bi = bi > NB - 1 ? NB - 1 : bi;
    return bi;
}

// ---------------------------------------------------------------------------
// Kernel 0: zero the histograms. grid = B*4, 1024 threads.
// ---------------------------------------------------------------------------
__global__ void __launch_bounds__(1024)
zero_kernel(int B) {
    const int i = blockIdx.x * 1024 + threadIdx.x;
    if (i < B * NB) g_hist[i] = 0;
}

// ---------------------------------------------------------------------------
// Kernel 1: histogram. grid = B*4 CTAs x 1024 threads, 1 element/thread.
// Atomics spread over 4096 distinct addresses per batch -> no contention.
// ---------------------------------------------------------------------------
__global__ void __launch_bounds__(1024)
hist_kernel(const float* __restrict__ t) {
    const int b   = blockIdx.x >> 2;              // 4 CTAs per batch
    const int idx = (blockIdx.x & 3) * 1024 + threadIdx.x;
    const float v = __ldg(t + (size_t)b * TT + idx);
    atomicAdd(&g_hist[b * NB + bucket_of(v)], 1);
}

// ---------------------------------------------------------------------------
// Kernel 2: exclusive scan of 4096 counts per batch. grid = B, 1024 threads.
// ---------------------------------------------------------------------------
__global__ void __launch_bounds__(1024, 1)
scan_kernel() {
    __shared__ int wsum[32];
    const int b   = blockIdx.x;
    const int tid = threadIdx.x;

    const int base = tid * 4;
    const int* hb = g_hist + b * NB;
    int s0 = __ldg(hb + base), s1 = __ldg(hb + base + 1);
    int s2 = __ldg(hb + base + 2), s3 = __ldg(hb + base + 3);
    int tot = s0 + s1 + s2 + s3;

    const int lane = tid & 31;
    const int wid  = tid >> 5;
    int v = tot;
    #pragma unroll
    for (int o = 1; o < 32; o <<= 1) {
        int u = __shfl_up_sync(0xFFFFFFFFu, v, o);
        if (lane >= o) v += u;
    }
    if (lane == 31) wsum[wid] = v;
    __syncthreads();
    if (wid == 0) {
        int w = wsum[lane];
        #pragma unroll
        for (int o = 1; o < 32; o <<= 1) {
            int u = __shfl_up_sync(0xFFFFFFFFu, w, o);
            if (lane >= o) w += u;
        }
        wsum[lane] = w;   // inclusive scan of per-warp totals
    }
    __syncthreads();

    int excl = v - tot + (wid > 0 ? wsum[wid - 1] : 0);
    const int st0 = excl, st1 = st0 + s0, st2 = st1 + s1, st3 = st2 + s2;

    int* gb = g_bstart + b * (NB + 1);
    int* gc = g_cur    + b * NB;
    gb[base] = st0; gb[base + 1] = st1; gb[base + 2] = st2; gb[base + 3] = st3;
    gc[base] = st0; gc[base + 1] = st1; gc[base + 2] = st2; gc[base + 3] = st3;
    if (tid == 0) gb[NB] = TT;
}

// ---------------------------------------------------------------------------
// Kernel 3: scatter. grid = B*4 CTAs x 1024 threads, 1 element/thread.
// ---------------------------------------------------------------------------
__global__ void __launch_bounds__(1024)
scatter_kernel(const float* __restrict__ t) {
    const int b   = blockIdx.x >> 2;
    const int idx = (blockIdx.x & 3) * 1024 + threadIdx.x;
    const float v = __ldg(t + (size_t)b * TT + idx);
    const int p = atomicAdd(&g_cur[b * NB + bucket_of(v)], 1);
    g_ct  [b * TT + p] = v;
    g_cidx[b * TT + p] = idx;
}

// ---------------------------------------------------------------------------
// Kernel 4: one warp per (QPW sorted queries, half of H). 8 warps / CTA.
// Warp tasks per batch: (TT/QPW) * 2 = 2048. hsel is the LOW bit so the two
// halves of the same query group sit in the same CTA (shared L1 rows).
// ---------------------------------------------------------------------------
__global__ void __launch_bounds__(256)
attn_kernel(const float* __restrict__ h, float* __restrict__ out) {
    const int gw   = (blockIdx.x * 256 + threadIdx.x) >> 5; // global warp id
    const int lane = threadIdx.x & 31;
    const int b    = gw >> 11;               // / 2048 tasks per batch
    const int task = gw & 2047;
    const int hsel = task & 1;               // which 128-col half
    const int p0   = (task >> 1) * QPW;      // first sorted position

    const float* ct = g_ct   + ((size_t)b << 12);
    const int*   ci = g_cidx + ((size_t)b << 12);

    float tq[QPW];
    int   iq[QPW];
    #pragma unroll
    for (int q = 0; q < QPW; ++q) {
        tq[q] = __ldg(ct + p0 + q);     // sorted: tq[0] <= ... <= tq[3]
        iq[q] = __ldg(ci + p0 + q);
    }

    // Union key window across the QPW queries.
    const int* gb = g_bstart + b * (NB + 1);
    const int lob = bucket_of(tq[0]) - RADIUS;
    const int hib = bucket_of(tq[QPW - 1]) + RADIUS + 1;
    const int lo = __ldg(gb + (lob < 0 ? 0 : lob));
    const int hi = __ldg(gb + (hib > NB ? NB : hib));

    // Base of this warp's half-row: cols [hsel*128, hsel*128+128).
    const float* hb = h + (((size_t)b << 12)) * HH + (hsel << 7);

    float4 acc[QPW];
    float  sumw[QPW];
    #pragma unroll
    for (int q = 0; q < QPW; ++q) {
        acc[q] = make_float4(0.f, 0.f, 0.f, 0.f);
        sumw[q] = 0.f;
    }

    #pragma unroll 2
    for (int j = lo; j < hi; ++j) {
        const float tk = __ldg(ct + j);
        const float4* row = (const float4*)(hb + (size_t)__ldg(ci + j) * HH);
        const float4 v = __ldg(row + lane);     // 4 cols per lane, 512B/warp

        #pragma unroll
        for (int q = 0; q < QPW; ++q) {
            const float d  = (float)TT * (tq[q] - tk);
            float d2 = d * d;
            // Out-of-cutoff -> EX2 input far below denormal range: weight
            // is unconditionally +0.0f.
            d2 = d2 > CUTF ? 999.0f : d2;
            const float w = __expf(-d2);
            sumw[q] += w;
            acc[q].x = fmaf(w, v.x, acc[q].x);
            acc[q].y = fmaf(w, v.y, acc[q].y);
            acc[q].z = fmaf(w, v.z, acc[q].z);
            acc[q].w = fmaf(w, v.w, acc[q].w);
        }
    }

    #pragma unroll
    for (int q = 0; q < QPW; ++q) {
        const float inv = 1.0f / sumw[q];  // sumw >= 1 (self key weight == 1)
        float4 o = make_float4(acc[q].x * inv, acc[q].y * inv,
                               acc[q].z * inv, acc[q].w * inv);
        float4* orow = (float4*)(out + ((size_t)(((size_t)b << 12) + iq[q])) * HH
                                 + (hsel << 7));
        orow[lane] = o;
    }
}

// ---------------------------------------------------------------------------
extern "C" void kernel_launch(void* const* d_in, const int* in_sizes, int n_in,
                              void* d_out, int out_size) {
    const float* h = (const float*)d_in[0];   // h_seq: (B, T, H) fp32
    const float* t = (const float*)d_in[1];   // t:     (B, T, 1) fp32
    float* out = (float*)d_out;               // (B, T, H) fp32

    int B = in_sizes[1] / TT;
    if (B < 1) B = 1;
    if (B > MAXB) B = MAXB;

    zero_kernel   <<<(B * NB + 1023) / 1024, 1024>>>(B);
    hist_kernel   <<<B * 4, 1024>>>(t);
    scan_kernel   <<<B, 1024>>>();
    scatter_kernel<<<B * 4, 1024>>>(t);
    // B * 2048 warp tasks, 8 warps per CTA.
    attn_kernel   <<<B * 2048 / 8, 256>>>(h, out);
}

// round 13
// speedup vs baseline: 1.0935x; 1.0935x over previous
#include <cuda_runtime.h>
#include <cuda_bf16.h>

// SoftTimeAttention: out[b,i,:] = sum_j w_ij * h[b,j,:],
//   w_ij = softmax_j( -(T*(t_i - t_j))^2 ), T=4096, tau=1.
// Only ~13/4096 keys per query have fp32-visible weight (cutoff d^2<=40
// drops <2e-14 relative mass; self key weight is exactly 1, sumw >= 1).
//
// R9 post-mortem: splitting the sort into 5 small kernels REGRESSED
// (global-atomic scatter alone 5.4us @ issue=4.9%). Reverted to the R5
// fused single-CTA smem counting sort (measured 4.2us).
// Attention: one warp per (4 consecutive sorted queries) x (half of H) —
// fix for R5's measured occ=28% / all-pipes-idle latency bound.

#define TT 4096            // sequence length (== softmax scale T)
#define HH 256             // head dim
#define NB 4096            // buckets
#define RADIUS 7           // ceil(sqrt(40)/TT * NB) = 7
#define CUTF 40.0f
#define MAXB 8
#define QPW 4              // sorted queries per warp

__device__ float g_ct  [MAXB * TT];         // t values reordered by bucket
__device__ int   g_cidx[MAXB * TT];         // original indices reordered
__device__ int   g_bstart[MAXB * (NB + 1)]; // bucket start offsets (+ total)

__device__ __forceinline__ int bucket_of(float v) {
    int bi = (int)(v * (float)NB);
    bi = bi < 0 ? 0 : bi;
    bi = bi > NB - 1 ? NB - 1 : bi;
    return bi;
}

// ---------------------------------------------------------------------------
// Kernel 1: fused counting sort by bucket. One 1024-thread CTA per batch.
// (R5-measured: 4.2us. smem atomics, single launch.)
// ---------------------------------------------------------------------------
__global__ void __launch_bounds__(1024, 1)
bucket_kernel(const float* __restrict__ t) {
    __shared__ int hist[NB];   // counts -> exclusive starts
    __shared__ int cur[NB];    // scatter cursors
    __shared__ int wsum[32];

    const int b   = blockIdx.x;
    const int tid = threadIdx.x;             // 1024 threads
    const float4* tb4 = (const float4*)(t + (size_t)b * TT);

    for (int i = tid; i < NB; i += 1024) hist[i] = 0;
    __syncthreads();

    // One float4 per thread covers TT = 4096 exactly.
    const float4 tv = __ldg(tb4 + tid);
    atomicAdd(&hist[bucket_of(tv.x)], 1);
    atomicAdd(&hist[bucket_of(tv.y)], 1);
    atomicAdd(&hist[bucket_of(tv.z)], 1);
    atomicAdd(&hist[bucket_of(tv.w)], 1);
    __syncthreads();

    // Hierarchical exclusive scan over 4096 counts (4 per thread).
    const int base = tid * 4;
    int s0 = hist[base], s1 = hist[base + 1], s2 = hist[base + 2], s3 = hist[base + 3];
    int tot = s0 + s1 + s2 + s3;

    const int lane = tid & 31;
    const int wid  = tid >> 5;
    int v = tot;
    #pragma unroll
    for (int o = 1; o < 32; o <<= 1) {
        int u = __shfl_up_sync(0xFFFFFFFFu, v, o);
        if (lane >= o) v += u;
    }
    if (lane == 31) wsum[wid] = v;
    __syncthreads();
    if (wid == 0) {
        int w = wsum[lane];
        #pragma unroll
        for (int o = 1; o < 32; o <<= 1) {
            int u = __shfl_up_sync(0xFFFFFFFFu, w, o);
            if (lane >= o) w += u;
        }
        wsum[lane] = w;   // inclusive scan of per-warp totals
    }
    __syncthreads();

    int excl = v - tot + (wid > 0 ? wsum[wid - 1] : 0);
    const int st0 = excl, st1 = st0 + s0, st2 = st1 + s1, st3 = st2 + s2;

    cur[base] = st0; cur[base + 1] = st1; cur[base + 2] = st2; cur[base + 3] = st3;

    int* gb = g_bstart + b * (NB + 1);
    gb[base] = st0; gb[base + 1] = st1; gb[base + 2] = st2; gb[base + 3] = st3;
    if (tid == 0) gb[NB] = TT;
    __syncthreads();

    // Scatter t and original index by bucket (reuse the registered float4).
    float* ct = g_ct   + b * TT;
    int*   ci = g_cidx + b * TT;
    {
        const int i0 = tid * 4;
        int p;
        p = atomicAdd(&cur[bucket_of(tv.x)], 1); ct[p] = tv.x; ci[p] = i0 + 0;
        p = atomicAdd(&cur[bucket_of(tv.y)], 1); ct[p] = tv.y; ci[p] = i0 + 1;
        p = atomicAdd(&cur[bucket_of(tv.z)], 1); ct[p] = tv.z; ci[p] = i0 + 2;
        p = atomicAdd(&cur[bucket_of(tv.w)], 1); ct[p] = tv.w; ci[p] = i0 + 3;
    }
}

// ---------------------------------------------------------------------------
// Kernel 2: one warp per (QPW sorted queries, half of H). 8 warps / CTA.
// Warp tasks per batch: (TT/QPW) * 2 = 2048. hsel is the LOW bit so the two
// halves of the same query group sit in the same CTA (shared L1 rows).
// ---------------------------------------------------------------------------
__global__ void __launch_bounds__(256)
attn_kernel(const float* __restrict__ h, float* __restrict__ out) {
    const int gw   = (blockIdx.x * 256 + threadIdx.x) >> 5; // global warp id
    const int lane = threadIdx.x & 31;
    const int b    = gw >> 11;               // / 2048 tasks per batch
    const int task = gw & 2047;
    const int hsel = task & 1;               // which 128-col half
    const int p0   = (task >> 1) * QPW;      // first sorted position

    const float* ct = g_ct   + ((size_t)b << 12);
    const int*   ci = g_cidx + ((size_t)b << 12);

    float tq[QPW];
    int   iq[QPW];
    #pragma unroll
    for (int q = 0; q < QPW; ++q) {
        tq[q] = __ldg(ct + p0 + q);     // sorted: tq[0] <= ... <= tq[3]
        iq[q] = __ldg(ci + p0 + q);
    }

    // Union key window across the QPW queries.
    const int* gb = g_bstart + b * (NB + 1);
    const int lob = bucket_of(tq[0]) - RADIUS;
    const int hib = bucket_of(tq[QPW - 1]) + RADIUS + 1;
    const int lo = __ldg(gb + (lob < 0 ? 0 : lob));
    const int hi = __ldg(gb + (hib > NB ? NB : hib));

    // Base of this warp's half-row: cols [hsel*128, hsel*128+128).
    const float* hb = h + (((size_t)b << 12)) * HH + (hsel << 7);

    float4 acc[QPW];
    float  sumw[QPW];
    #pragma unroll
    for (int q = 0; q < QPW; ++q) {
        acc[q] = make_float4(0.f, 0.f, 0.f, 0.f);
        sumw[q] = 0.f;
    }

    #pragma unroll 2
    for (int j = lo; j < hi; ++j) {
        const float tk = __ldg(ct + j);
        const float4* row = (const float4*)(hb + (size_t)__ldg(ci + j) * HH);
        const float4 v = __ldg(row + lane);     // 4 cols per lane, 512B/warp

        #pragma unroll
        for (int q = 0; q < QPW; ++q) {
            const float d  = (float)TT * (tq[q] - tk);
            float d2 = d * d;
            // Out-of-cutoff -> EX2 input far below denormal range: weight
            // is unconditionally +0.0f.
            d2 = d2 > CUTF ? 999.0f : d2;
            const float w = __expf(-d2);
            sumw[q] += w;
            acc[q].x = fmaf(w, v.x, acc[q].x);
            acc[q].y = fmaf(w, v.y, acc[q].y);
            acc[q].z = fmaf(w, v.z, acc[q].z);
            acc[q].w = fmaf(w, v.w, acc[q].w);
        }
    }

    #pragma unroll
    for (int q = 0; q < QPW; ++q) {
        const float inv = 1.0f / sumw[q];  // sumw >= 1 (self key weight == 1)
        float4 o = make_float4(acc[q].x * inv, acc[q].y * inv,
                               acc[q].z * inv, acc[q].w * inv);
        float4* orow = (float4*)(out + ((size_t)(((size_t)b << 12) + iq[q])) * HH
                                 + (hsel << 7));
        orow[lane] = o;
    }
}

// ---------------------------------------------------------------------------
extern "C" void kernel_launch(void* const* d_in, const int* in_sizes, int n_in,
                              void* d_out, int out_size) {
    const float* h = (const float*)d_in[0];   // h_seq: (B, T, H) fp32
    const float* t = (const float*)d_in[1];   // t:     (B, T, 1) fp32
    float* out = (float*)d_out;               // (B, T, H) fp32

    int B = in_sizes[1] / TT;
    if (B < 1) B = 1;
    if (B > MAXB) B = MAXB;

    bucket_kernel<<<B, 1024>>>(t);
    // B * 2048 warp tasks, 8 warps per CTA.
    attn_kernel<<<B * 2048 / 8, 256>>>(h, out);
}